// round 7
// baseline (speedup 1.0000x reference)
#include <cuda_runtime.h>

#define Bc 8
#define Sc 1024
#define DMc 512
#define Hc 8
#define Dc 64

// ---------------- device scratch ----------------
__device__ float g_Q[Bc*Hc*Sc*Dc];          // [bh][s][d]
__device__ float g_K[Bc*Hc*Sc*Dc];          // [bh][s][d]
__device__ float g_V[Bc*Hc*Sc*Dc];          // [bh][s][d]
__device__ float g_Vt[Bc*Hc*Dc*Sc];         // [bh][d][s]
__device__ float g_ctx[Bc*Sc*DMc];          // [b*s][512]
__device__ float g_Wt[4*DMc*DMc];           // [which][n][k]
__device__ unsigned char g_mask8[Bc*Sc*Sc]; // compressed mask

__device__ __forceinline__ unsigned f2tf(float x) {
    unsigned u;
    asm("cvt.rna.tf32.f32 %0, %1;" : "=r"(u) : "f"(x));
    return u;
}

__device__ __forceinline__ void mma8(float* c, const unsigned* a, const unsigned* b) {
    asm volatile(
        "mma.sync.aligned.m16n8k8.row.col.f32.tf32.tf32.f32 "
        "{%0,%1,%2,%3}, {%4,%5,%6,%7}, {%8,%9}, {%0,%1,%2,%3};"
        : "+f"(c[0]), "+f"(c[1]), "+f"(c[2]), "+f"(c[3])
        : "r"(a[0]), "r"(a[1]), "r"(a[2]), "r"(a[3]), "r"(b[0]), "r"(b[1]));
}

// ---------------- mask compress: int32 -> u8 ----------------
__global__ void mask8_kernel(const int* __restrict__ mask)
{
    int i = blockIdx.x * blockDim.x + threadIdx.x;   // 2M int4 groups
    int4 v = ((const int4*)mask)[i];
    ((uchar4*)g_mask8)[i] = make_uchar4((unsigned char)v.x, (unsigned char)v.y,
                                        (unsigned char)v.z, (unsigned char)v.w);
}

// ---------------- transpose W: g_Wt[i][n][k] = W_i[k][n] ----------------
__global__ void transpose_w(const float* __restrict__ W0, const float* __restrict__ W1,
                            const float* __restrict__ W2, const float* __restrict__ W3)
{
    __shared__ float t[32][33];
    const float* W = (blockIdx.z == 0) ? W0 : (blockIdx.z == 1) ? W1 : (blockIdx.z == 2) ? W2 : W3;
    float* out = g_Wt + blockIdx.z * DMc * DMc;
    int x0 = blockIdx.x * 32, y0 = blockIdx.y * 32;
    int tx = threadIdx.x, ty = threadIdx.y;
#pragma unroll
    for (int j = 0; j < 32; j += 8) t[ty + j][tx] = W[(y0 + ty + j) * DMc + x0 + tx];
    __syncthreads();
#pragma unroll
    for (int j = 0; j < 32; j += 8) out[(x0 + ty + j) * DMc + y0 + tx] = t[tx][ty + j];
}

// ---------------- transpose V: g_Vt[bh][d][s] = g_V[bh][s][d] ----------------
__global__ void transpose_v()
{
    __shared__ float t[32][33];
    int bh = blockIdx.z;
    int s0 = blockIdx.x * 32, d0 = blockIdx.y * 32;
    const float* V = g_V + bh * Sc * Dc;
    float* Vt = g_Vt + bh * Dc * Sc;
    int tx = threadIdx.x, ty = threadIdx.y;
#pragma unroll
    for (int j = 0; j < 32; j += 8) t[ty + j][tx] = V[(s0 + ty + j) * Dc + d0 + tx];
    __syncthreads();
#pragma unroll
    for (int j = 0; j < 32; j += 8) Vt[(d0 + ty + j) * Sc + s0 + tx] = t[tx][ty + j];
}

// ---------------- fused QKV projection (tf32 MMA, double-buffered) -----------
// blockIdx.z = sel in {0,1,2}; stores remapped into g_Q/g_K/g_V [bh][s][d]
__global__ __launch_bounds__(256) void proj_mma(const float* __restrict__ A0,
                                                const float* __restrict__ A1,
                                                const float* __restrict__ A2)
{
    extern __shared__ unsigned dyn[];
    int sel = blockIdx.z;
    const float* Ap = (sel == 0) ? A0 : (sel == 1) ? A1 : A2;
    const float* Wt = g_Wt + sel * DMc * DMc;

    int tid = threadIdx.x;
    int w = tid >> 5, lane = tid & 31, gid = lane >> 2, qid = lane & 3;
    int warp_m = (w >> 2) * 64, warp_n = (w & 3) * 32;
    int m0 = blockIdx.y * 128, n0 = blockIdx.x * 128;

    float2 ra[8], rb[8];
    float acc[4][4][4];
#pragma unroll
    for (int i = 0; i < 4; i++)
#pragma unroll
        for (int j = 0; j < 4; j++)
#pragma unroll
            for (int r = 0; r < 4; r++) acc[i][j][r] = 0.f;

#pragma unroll
    for (int u = 0; u < 8; u++) {
        int e = tid + 256 * u;
        int m = e >> 4, k2 = e & 15;
        ra[u] = *(const float2*)&Ap[(m0 + m) * 512 + 2 * k2];
        rb[u] = *(const float2*)&Wt[(n0 + m) * 512 + 2 * k2];
    }
#pragma unroll
    for (int u = 0; u < 8; u++) {
        int e = tid + 256 * u;
        int m = e >> 4, k2 = e & 15;
        *(uint2*)&dyn[m * 36 + 2 * k2] = make_uint2(f2tf(ra[u].x), f2tf(ra[u].y));
        *(uint2*)&dyn[128 * 36 + m * 36 + 2 * k2] = make_uint2(f2tf(rb[u].x), f2tf(rb[u].y));
    }
    __syncthreads();

    int buf = 0;
    for (int kt = 0; kt < 512; kt += 32) {
        bool more = (kt + 32) < 512;
        if (more) {
#pragma unroll
            for (int u = 0; u < 8; u++) {
                int e = tid + 256 * u;
                int m = e >> 4, k2 = e & 15;
                ra[u] = *(const float2*)&Ap[(m0 + m) * 512 + kt + 32 + 2 * k2];
                rb[u] = *(const float2*)&Wt[(n0 + m) * 512 + kt + 32 + 2 * k2];
            }
        }
        {
            unsigned* Asb = dyn + buf * 2 * 128 * 36;
            unsigned* Bsb = Asb + 128 * 36;
#pragma unroll
            for (int ks = 0; ks < 4; ks++) {
                unsigned a[4][4], b[4][2];
#pragma unroll
                for (int mf = 0; mf < 4; mf++) {
                    int r = warp_m + mf * 16 + gid;
                    a[mf][0] = Asb[r * 36 + ks * 8 + qid];
                    a[mf][1] = Asb[(r + 8) * 36 + ks * 8 + qid];
                    a[mf][2] = Asb[r * 36 + ks * 8 + qid + 4];
                    a[mf][3] = Asb[(r + 8) * 36 + ks * 8 + qid + 4];
                }
#pragma unroll
                for (int nf = 0; nf < 4; nf++) {
                    int r = warp_n + nf * 8 + gid;
                    b[nf][0] = Bsb[r * 36 + ks * 8 + qid];
                    b[nf][1] = Bsb[r * 36 + ks * 8 + qid + 4];
                }
#pragma unroll
                for (int mf = 0; mf < 4; mf++)
#pragma unroll
                    for (int nf = 0; nf < 4; nf++)
                        mma8(acc[mf][nf], a[mf], b[nf]);
            }
        }
        if (more) {
            unsigned* Asb = dyn + (buf ^ 1) * 2 * 128 * 36;
            unsigned* Bsb = Asb + 128 * 36;
#pragma unroll
            for (int u = 0; u < 8; u++) {
                int e = tid + 256 * u;
                int m = e >> 4, k2 = e & 15;
                *(uint2*)&Asb[m * 36 + 2 * k2] = make_uint2(f2tf(ra[u].x), f2tf(ra[u].y));
                *(uint2*)&Bsb[m * 36 + 2 * k2] = make_uint2(f2tf(rb[u].x), f2tf(rb[u].y));
            }
        }
        __syncthreads();
        buf ^= 1;
    }

    float* dst = (sel == 0) ? g_Q : (sel == 1) ? g_K : g_V;
#pragma unroll
    for (int mf = 0; mf < 4; mf++)
#pragma unroll
        for (int nf = 0; nf < 4; nf++) {
            int m = m0 + warp_m + mf * 16 + gid;
            int n = n0 + warp_n + nf * 8 + qid * 2;
            int b_ = m >> 10, s = m & 1023;
            int h = n >> 6, d = n & 63;
            *(float2*)&dst[((b_ * Hc + h) * Sc + s) * Dc + d] =
                make_float2(acc[mf][nf][0], acc[mf][nf][1]);
            *(float2*)&dst[((b_ * Hc + h) * Sc + s + 8) * Dc + d] =
                make_float2(acc[mf][nf][2], acc[mf][nf][3]);
        }
}

// ---------------- fc GEMM: out = g_ctx @ W_fc ----------------
__global__ __launch_bounds__(256) void fc_mma(float* __restrict__ Cplain)
{
    extern __shared__ unsigned dyn[];
    const float* Ap = g_ctx;
    const float* Wt = g_Wt + 3 * DMc * DMc;

    int tid = threadIdx.x;
    int w = tid >> 5, lane = tid & 31, gid = lane >> 2, qid = lane & 3;
    int warp_m = (w >> 2) * 64, warp_n = (w & 3) * 32;
    int m0 = blockIdx.y * 128, n0 = blockIdx.x * 128;

    float2 ra[8], rb[8];
    float acc[4][4][4];
#pragma unroll
    for (int i = 0; i < 4; i++)
#pragma unroll
        for (int j = 0; j < 4; j++)
#pragma unroll
            for (int r = 0; r < 4; r++) acc[i][j][r] = 0.f;

#pragma unroll
    for (int u = 0; u < 8; u++) {
        int e = tid + 256 * u;
        int m = e >> 4, k2 = e & 15;
        ra[u] = *(const float2*)&Ap[(m0 + m) * 512 + 2 * k2];
        rb[u] = *(const float2*)&Wt[(n0 + m) * 512 + 2 * k2];
    }
#pragma unroll
    for (int u = 0; u < 8; u++) {
        int e = tid + 256 * u;
        int m = e >> 4, k2 = e & 15;
        *(uint2*)&dyn[m * 36 + 2 * k2] = make_uint2(f2tf(ra[u].x), f2tf(ra[u].y));
        *(uint2*)&dyn[128 * 36 + m * 36 + 2 * k2] = make_uint2(f2tf(rb[u].x), f2tf(rb[u].y));
    }
    __syncthreads();

    int buf = 0;
    for (int kt = 0; kt < 512; kt += 32) {
        bool more = (kt + 32) < 512;
        if (more) {
#pragma unroll
            for (int u = 0; u < 8; u++) {
                int e = tid + 256 * u;
                int m = e >> 4, k2 = e & 15;
                ra[u] = *(const float2*)&Ap[(m0 + m) * 512 + kt + 32 + 2 * k2];
                rb[u] = *(const float2*)&Wt[(n0 + m) * 512 + kt + 32 + 2 * k2];
            }
        }
        {
            unsigned* Asb = dyn + buf * 2 * 128 * 36;
            unsigned* Bsb = Asb + 128 * 36;
#pragma unroll
            for (int ks = 0; ks < 4; ks++) {
                unsigned a[4][4], b[4][2];
#pragma unroll
                for (int mf = 0; mf < 4; mf++) {
                    int r = warp_m + mf * 16 + gid;
                    a[mf][0] = Asb[r * 36 + ks * 8 + qid];
                    a[mf][1] = Asb[(r + 8) * 36 + ks * 8 + qid];
                    a[mf][2] = Asb[r * 36 + ks * 8 + qid + 4];
                    a[mf][3] = Asb[(r + 8) * 36 + ks * 8 + qid + 4];
                }
#pragma unroll
                for (int nf = 0; nf < 4; nf++) {
                    int r = warp_n + nf * 8 + gid;
                    b[nf][0] = Bsb[r * 36 + ks * 8 + qid];
                    b[nf][1] = Bsb[r * 36 + ks * 8 + qid + 4];
                }
#pragma unroll
                for (int mf = 0; mf < 4; mf++)
#pragma unroll
                    for (int nf = 0; nf < 4; nf++)
                        mma8(acc[mf][nf], a[mf], b[nf]);
            }
        }
        if (more) {
            unsigned* Asb = dyn + (buf ^ 1) * 2 * 128 * 36;
            unsigned* Bsb = Asb + 128 * 36;
#pragma unroll
            for (int u = 0; u < 8; u++) {
                int e = tid + 256 * u;
                int m = e >> 4, k2 = e & 15;
                *(uint2*)&Asb[m * 36 + 2 * k2] = make_uint2(f2tf(ra[u].x), f2tf(ra[u].y));
                *(uint2*)&Bsb[m * 36 + 2 * k2] = make_uint2(f2tf(rb[u].x), f2tf(rb[u].y));
            }
        }
        __syncthreads();
        buf ^= 1;
    }

#pragma unroll
    for (int mf = 0; mf < 4; mf++)
#pragma unroll
        for (int nf = 0; nf < 4; nf++) {
            int m = m0 + warp_m + mf * 16 + gid;
            int n = n0 + warp_n + nf * 8 + qid * 2;
            *(float2*)&Cplain[m * 512 + n] = make_float2(acc[mf][nf][0], acc[mf][nf][1]);
            *(float2*)&Cplain[(m + 8) * 512 + n] = make_float2(acc[mf][nf][2], acc[mf][nf][3]);
        }
}

// ---------------- avg GEMM: out_avg = mask? -1e9 : Qfull.Kfull/64 + edge -----
// Heads partition the 512 dims: sum_h (QK/8)/8 == full 512-dot / 64.
// grid (ktile 8, qtile 8, b 8), block 256, k-loop 512 via (h,d), double-buffered
__global__ __launch_bounds__(256) void avg_mma(const float* __restrict__ edge,
                                               float* __restrict__ out_avg)
{
    extern __shared__ unsigned dyn[];
    int tid = threadIdx.x;
    int w = tid >> 5, lane = tid & 31, gid = lane >> 2, qid = lane & 3;
    int warp_m = (w >> 2) * 64, warp_n = (w & 3) * 32;
    int k0 = blockIdx.x * 128, q0 = blockIdx.y * 128, b = blockIdx.z;

    float2 ra[8], rb[8];
    float acc[4][4][4];
#pragma unroll
    for (int i = 0; i < 4; i++)
#pragma unroll
        for (int j = 0; j < 4; j++)
#pragma unroll
            for (int r = 0; r < 4; r++) acc[i][j][r] = 0.f;

    // prologue: kt = 0 (h=0, d0=0)
#pragma unroll
    for (int u = 0; u < 8; u++) {
        int e = tid + 256 * u;
        int m = e >> 4, k2 = e & 15;
        ra[u] = *(const float2*)&g_Q[((size_t)(b * 8 + 0) * Sc + q0 + m) * Dc + 2 * k2];
        rb[u] = *(const float2*)&g_K[((size_t)(b * 8 + 0) * Sc + k0 + m) * Dc + 2 * k2];
    }
#pragma unroll
    for (int u = 0; u < 8; u++) {
        int e = tid + 256 * u;
        int m = e >> 4, k2 = e & 15;
        *(uint2*)&dyn[m * 36 + 2 * k2] = make_uint2(f2tf(ra[u].x), f2tf(ra[u].y));
        *(uint2*)&dyn[128 * 36 + m * 36 + 2 * k2] = make_uint2(f2tf(rb[u].x), f2tf(rb[u].y));
    }
    __syncthreads();

    int buf = 0;
    for (int kt = 0; kt < 512; kt += 32) {
        bool more = (kt + 32) < 512;
        if (more) {
            int kn = kt + 32;
            int h = kn >> 6, d0 = kn & 63;
#pragma unroll
            for (int u = 0; u < 8; u++) {
                int e = tid + 256 * u;
                int m = e >> 4, k2 = e & 15;
                ra[u] = *(const float2*)&g_Q[((size_t)(b * 8 + h) * Sc + q0 + m) * Dc + d0 + 2 * k2];
                rb[u] = *(const float2*)&g_K[((size_t)(b * 8 + h) * Sc + k0 + m) * Dc + d0 + 2 * k2];
            }
        }
        {
            unsigned* Asb = dyn + buf * 2 * 128 * 36;
            unsigned* Bsb = Asb + 128 * 36;
#pragma unroll
            for (int ks = 0; ks < 4; ks++) {
                unsigned a[4][4], bfr[4][2];
#pragma unroll
                for (int mf = 0; mf < 4; mf++) {
                    int r = warp_m + mf * 16 + gid;
                    a[mf][0] = Asb[r * 36 + ks * 8 + qid];
                    a[mf][1] = Asb[(r + 8) * 36 + ks * 8 + qid];
                    a[mf][2] = Asb[r * 36 + ks * 8 + qid + 4];
                    a[mf][3] = Asb[(r + 8) * 36 + ks * 8 + qid + 4];
                }
#pragma unroll
                for (int nf = 0; nf < 4; nf++) {
                    int r = warp_n + nf * 8 + gid;
                    bfr[nf][0] = Bsb[r * 36 + ks * 8 + qid];
                    bfr[nf][1] = Bsb[r * 36 + ks * 8 + qid + 4];
                }
#pragma unroll
                for (int mf = 0; mf < 4; mf++)
#pragma unroll
                    for (int nf = 0; nf < 4; nf++)
                        mma8(acc[mf][nf], a[mf], bfr[nf]);
            }
        }
        if (more) {
            unsigned* Asb = dyn + (buf ^ 1) * 2 * 128 * 36;
            unsigned* Bsb = Asb + 128 * 36;
#pragma unroll
            for (int u = 0; u < 8; u++) {
                int e = tid + 256 * u;
                int m = e >> 4, k2 = e & 15;
                *(uint2*)&Asb[m * 36 + 2 * k2] = make_uint2(f2tf(ra[u].x), f2tf(ra[u].y));
                *(uint2*)&Bsb[m * 36 + 2 * k2] = make_uint2(f2tf(rb[u].x), f2tf(rb[u].y));
            }
        }
        __syncthreads();
        buf ^= 1;
    }

#pragma unroll
    for (int mf = 0; mf < 4; mf++)
#pragma unroll
        for (int nf = 0; nf < 4; nf++) {
            int q = q0 + warp_m + mf * 16 + gid;
            int kc = k0 + warp_n + nf * 8 + qid * 2;
#pragma unroll
            for (int half = 0; half < 2; half++) {
                int qq = q + half * 8;
                size_t row = (size_t)(b * Sc + qq) * Sc;
                float2 ev = *(const float2*)&edge[row + kc];
                uchar2 mk = *(const uchar2*)&g_mask8[row + kc];
                float c0 = acc[mf][nf][half * 2 + 0];
                float c1 = acc[mf][nf][half * 2 + 1];
                float2 o;
                o.x = mk.x ? -1e9f : c0 * 0.015625f + ev.x;
                o.y = mk.y ? -1e9f : c1 * 0.015625f + ev.y;
                *(float2*)&out_avg[row + kc] = o;
            }
        }
}

// ---------------- flash attention: fused scores+softmax+AV -------------------
// grid (qtile 8, bh 64), block 256 (8 warps x 16 q-rows). Chunks of 64 keys.
__global__ __launch_bounds__(256, 1) void flash_mma(const float* __restrict__ edge)
{
    extern __shared__ unsigned fsm[];
    unsigned (*Ps)[68] = (unsigned(*)[68])fsm;               // 128 rows (Q staging, then P)
    unsigned (*Ks)[68] = (unsigned(*)[68])(fsm + 128 * 68);  // 2 x 64 rows
    unsigned (*Vs)[68] = (unsigned(*)[68])(fsm + 256 * 68);  // 2 x 64 rows

    int tid = threadIdx.x;
    int w = tid >> 5, lane = tid & 31, gid = lane >> 2, qid = lane & 3;
    int q0 = blockIdx.x * 128, bh = blockIdx.y;
    int b = bh >> 3, h = bh & 7;

    const float* Qg  = g_Q + ((size_t)bh * Sc + q0) * Dc;
    const float* Kg  = g_K + (size_t)bh * Sc * Dc;
    const float* Vtg = g_Vt + (size_t)bh * Dc * Sc;

    // stage Q -> Ps, and K/V chunk 0
#pragma unroll
    for (int u = 0; u < 16; u++) {
        int e = tid + 256 * u;
        int r = e >> 5, c2 = e & 31;
        float2 v = *(const float2*)&Qg[r * Dc + 2 * c2];
        *(uint2*)&Ps[r][2 * c2] = make_uint2(f2tf(v.x), f2tf(v.y));
    }
#pragma unroll
    for (int u = 0; u < 8; u++) {
        int e = tid + 256 * u;
        int r = e >> 5, c2 = e & 31;
        float2 kv = *(const float2*)&Kg[r * Dc + 2 * c2];
        float2 vv = *(const float2*)&Vtg[r * Sc + 2 * c2];
        *(uint2*)&Ks[r][2 * c2] = make_uint2(f2tf(kv.x), f2tf(kv.y));
        *(uint2*)&Vs[r][2 * c2] = make_uint2(f2tf(vv.x), f2tf(vv.y));
    }
    __syncthreads();

    // Q fragments resident in registers
    unsigned qf[8][4];
    int r0 = w * 16 + gid;
#pragma unroll
    for (int ks = 0; ks < 8; ks++) {
        qf[ks][0] = Ps[r0][ks * 8 + qid];
        qf[ks][1] = Ps[r0 + 8][ks * 8 + qid];
        qf[ks][2] = Ps[r0][ks * 8 + qid + 4];
        qf[ks][3] = Ps[r0 + 8][ks * 8 + qid + 4];
    }
    __syncwarp();

    const float* eb0 = edge + ((size_t)(b * Sc) + q0 + w * 16 + gid) * Sc;
    const float* eb1 = eb0 + 8 * Sc;
    const unsigned char* mb0 = g_mask8 + ((size_t)(b * Sc) + q0 + w * 16 + gid) * Sc;
    const unsigned char* mb1 = mb0 + 8 * Sc;

    float m0 = -1e30f, m1 = -1e30f, l0 = 0.f, l1 = 0.f;
    float of[8][4];
#pragma unroll
    for (int nf = 0; nf < 8; nf++)
#pragma unroll
        for (int r = 0; r < 4; r++) of[nf][r] = 0.f;

    int buf = 0;
    for (int ch = 0; ch < 16; ch++) {
        int kt = ch * 64;

        // prefetch next K/V chunk into regs
        float2 kst[8], vst[8];
        if (ch < 15) {
#pragma unroll
            for (int u = 0; u < 8; u++) {
                int e = tid + 256 * u;
                int r = e >> 5, c2 = e & 31;
                kst[u] = *(const float2*)&Kg[(kt + 64 + r) * Dc + 2 * c2];
                vst[u] = *(const float2*)&Vtg[r * Sc + kt + 64 + 2 * c2];
            }
        }
        // prefetch edge/mask for this chunk
        float2 ef0[8], ef1[8];
        uchar2 mk0[8], mk1[8];
#pragma unroll
        for (int nf = 0; nf < 8; nf++) {
            int c = kt + nf * 8 + 2 * qid;
            ef0[nf] = *(const float2*)&eb0[c];
            ef1[nf] = *(const float2*)&eb1[c];
            mk0[nf] = *(const uchar2*)&mb0[c];
            mk1[nf] = *(const uchar2*)&mb1[c];
        }

        // S = Q K^T (16q x 64k per warp)
        float sa[8][4];
#pragma unroll
        for (int nf = 0; nf < 8; nf++)
#pragma unroll
            for (int r = 0; r < 4; r++) sa[nf][r] = 0.f;
#pragma unroll
        for (int ks = 0; ks < 8; ks++) {
#pragma unroll
            for (int nf = 0; nf < 8; nf++) {
                unsigned bb[2];
                bb[0] = Ks[buf * 64 + nf * 8 + gid][ks * 8 + qid];
                bb[1] = Ks[buf * 64 + nf * 8 + gid][ks * 8 + qid + 4];
                mma8(sa[nf], qf[ks], bb);
            }
        }

        // epilogue: scale + edge + mask, online softmax
        float tm0 = -1e30f, tm1 = -1e30f;
#pragma unroll
        for (int nf = 0; nf < 8; nf++) {
            sa[nf][0] = mk0[nf].x ? -1e9f : sa[nf][0] * 0.125f + ef0[nf].x;
            sa[nf][1] = mk0[nf].y ? -1e9f : sa[nf][1] * 0.125f + ef0[nf].y;
            sa[nf][2] = mk1[nf].x ? -1e9f : sa[nf][2] * 0.125f + ef1[nf].x;
            sa[nf][3] = mk1[nf].y ? -1e9f : sa[nf][3] * 0.125f + ef1[nf].y;
            tm0 = fmaxf(tm0, fmaxf(sa[nf][0], sa[nf][1]));
            tm1 = fmaxf(tm1, fmaxf(sa[nf][2], sa[nf][3]));
        }
        tm0 = fmaxf(tm0, __shfl_xor_sync(0xffffffffu, tm0, 1));
        tm0 = fmaxf(tm0, __shfl_xor_sync(0xffffffffu, tm0, 2));
        tm1 = fmaxf(tm1, __shfl_xor_sync(0xffffffffu, tm1, 1));
        tm1 = fmaxf(tm1, __shfl_xor_sync(0xffffffffu, tm1, 2));
        float mn0 = fmaxf(m0, tm0), mn1 = fmaxf(m1, tm1);
        float a0 = __expf(m0 - mn0), a1 = __expf(m1 - mn1);
        float ts0 = 0.f, ts1 = 0.f;
#pragma unroll
        for (int nf = 0; nf < 8; nf++) {
            sa[nf][0] = __expf(sa[nf][0] - mn0);
            sa[nf][1] = __expf(sa[nf][1] - mn0);
            sa[nf][2] = __expf(sa[nf][2] - mn1);
            sa[nf][3] = __expf(sa[nf][3] - mn1);
            ts0 += sa[nf][0] + sa[nf][1];
            ts1 += sa[nf][2] + sa[nf][3];
            of[nf][0] *= a0; of[nf][1] *= a0;
            of[nf][2] *= a1; of[nf][3] *= a1;
        }
        ts0 += __shfl_xor_sync(0xffffffffu, ts0, 1);
        ts0 += __shfl_xor_sync(0xffffffffu, ts0, 2);
        ts1 += __shfl_xor_sync(0xffffffffu, ts1, 1);
        ts1 += __shfl_xor_sync(0xffffffffu, ts1, 2);
        l0 = l0 * a0 + ts0;
        l1 = l1 * a1 + ts1;
        m0 = mn0; m1 = mn1;

        // P -> smem (warp-private rows)
        __syncwarp();
#pragma unroll
        for (int nf = 0; nf < 8; nf++) {
            *(uint2*)&Ps[r0][nf * 8 + 2 * qid] =
                make_uint2(f2tf(sa[nf][0]), f2tf(sa[nf][1]));
            *(uint2*)&Ps[r0 + 8][nf * 8 + 2 * qid] =
                make_uint2(f2tf(sa[nf][2]), f2tf(sa[nf][3]));
        }
        __syncwarp();

        // O += P V
#pragma unroll
        for (int ks = 0; ks < 8; ks++) {
            unsigned pa[4];
            pa[0] = Ps[r0][ks * 8 + qid];
            pa[1] = Ps[r0 + 8][ks * 8 + qid];
            pa[2] = Ps[r0][ks * 8 + qid + 4];
            pa[3] = Ps[r0 + 8][ks * 8 + qid + 4];
#pragma unroll
            for (int nf = 0; nf < 8; nf++) {
                unsigned bb[2];
                bb[0] = Vs[buf * 64 + nf * 8 + gid][ks * 8 + qid];
                bb[1] = Vs[buf * 64 + nf * 8 + gid][ks * 8 + qid + 4];
                mma8(of[nf], pa, bb);
            }
        }

        // commit next K/V chunk
        if (ch < 15) {
#pragma unroll
            for (int u = 0; u < 8; u++) {
                int e = tid + 256 * u;
                int r = e >> 5, c2 = e & 31;
                *(uint2*)&Ks[(buf ^ 1) * 64 + r][2 * c2] = make_uint2(f2tf(kst[u].x), f2tf(kst[u].y));
                *(uint2*)&Vs[(buf ^ 1) * 64 + r][2 * c2] = make_uint2(f2tf(vst[u].x), f2tf(vst[u].y));
            }
        }
        __syncthreads();
        buf ^= 1;
    }

    float li0 = 1.f / l0, li1 = 1.f / l1;
    float* crow0 = g_ctx + ((size_t)(b * Sc) + q0 + w * 16 + gid) * DMc + h * Dc;
    float* crow1 = crow0 + 8 * DMc;
#pragma unroll
    for (int nf = 0; nf < 8; nf++) {
        *(float2*)&crow0[nf * 8 + 2 * qid] = make_float2(of[nf][0] * li0, of[nf][1] * li0);
        *(float2*)&crow1[nf * 8 + 2 * qid] = make_float2(of[nf][2] * li1, of[nf][3] * li1);
    }
}

// ---------------- launch ------------------------------------------------------
extern "C" void kernel_launch(void* const* d_in, const int* in_sizes, int n_in,
                              void* d_out, int out_size)
{
    (void)in_sizes; (void)n_in; (void)out_size;
    const float* inQ  = (const float*)d_in[0];
    const float* inK  = (const float*)d_in[1];
    const float* inV  = (const float*)d_in[2];
    const int*   mask = (const int*)d_in[3];
    const float* edge = (const float*)d_in[4];
    const float* WQ   = (const float*)d_in[5];
    const float* WK   = (const float*)d_in[6];
    const float* WV   = (const float*)d_in[7];
    const float* Wfc  = (const float*)d_in[8];

    float* out     = (float*)d_out;
    float* out_avg = out + Bc * Sc * DMc;

    const int GEMM_SMEM  = 2 * 2 * 128 * 36 * 4;   // 73728
    const int FLASH_SMEM = 384 * 68 * 4;           // 104448
    cudaFuncSetAttribute(proj_mma,  cudaFuncAttributeMaxDynamicSharedMemorySize, GEMM_SMEM);
    cudaFuncSetAttribute(fc_mma,    cudaFuncAttributeMaxDynamicSharedMemorySize, GEMM_SMEM);
    cudaFuncSetAttribute(avg_mma,   cudaFuncAttributeMaxDynamicSharedMemorySize, GEMM_SMEM);
    cudaFuncSetAttribute(flash_mma, cudaFuncAttributeMaxDynamicSharedMemorySize, FLASH_SMEM);

    transpose_w<<<dim3(16, 16, 4), dim3(32, 8)>>>(WQ, WK, WV, Wfc);
    mask8_kernel<<<8192, 256>>>(mask);

    proj_mma<<<dim3(4, 64, 3), 256, GEMM_SMEM>>>(inQ, inK, inV);
    transpose_v<<<dim3(32, 2, 64), dim3(32, 8)>>>();

    avg_mma<<<dim3(8, 8, 8), 256, GEMM_SMEM>>>(edge, out_avg);
    flash_mma<<<dim3(8, 64), 256, FLASH_SMEM>>>(edge);

    fc_mma<<<dim3(4, 64), 256, GEMM_SMEM>>>(out);
}